// round 8
// baseline (speedup 1.0000x reference)
#include <cuda_runtime.h>
#include <cuda_fp16.h>
#include <cstdint>

#define DM 4096
#define TOKS 4096
#define NELEM (TOKS * DM)

// Scratch (allocation-free rule: __device__ globals)
__device__ __half g_q[NELEM];    // Q (b,h,s,d) half
__device__ __half g_k[NELEM];    // K (b,h,s,d) half
__device__ __half g_v[NELEM];    // V (b,h,s,d) half
__device__ __half g_ah[NELEM];   // attention output (b,s,h,d) half
__device__ __half g_xh[NELEM];   // half activations
__device__ __half g_wqh[NELEM];
__device__ __half g_wkh[NELEM];
__device__ __half g_wvh[NELEM];
__device__ __half g_woh[NELEM];

__device__ __forceinline__ void ldsm4(unsigned &d0, unsigned &d1, unsigned &d2, unsigned &d3,
                                      const void *p) {
    uint32_t addr = (uint32_t)__cvta_generic_to_shared(p);
    asm volatile("ldmatrix.sync.aligned.m8n8.x4.shared.b16 {%0,%1,%2,%3}, [%4];"
                 : "=r"(d0), "=r"(d1), "=r"(d2), "=r"(d3)
                 : "r"(addr));
}

__device__ __forceinline__ void mma16(float c[4], const unsigned a[4], unsigned b0, unsigned b1) {
    asm volatile("mma.sync.aligned.m16n8k16.row.col.f32.f16.f16.f32 "
                 "{%0,%1,%2,%3}, {%4,%5,%6,%7}, {%8,%9}, {%0,%1,%2,%3};"
                 : "+f"(c[0]), "+f"(c[1]), "+f"(c[2]), "+f"(c[3])
                 : "r"(a[0]), "r"(a[1]), "r"(a[2]), "r"(a[3]), "r"(b0), "r"(b1));
}

__device__ __forceinline__ void cp16(void *smem_dst, const void *gsrc) {
    uint32_t d = (uint32_t)__cvta_generic_to_shared(smem_dst);
    asm volatile("cp.async.cg.shared.global [%0], [%1], 16;\n" :: "r"(d), "l"(gsrc));
}

// ---------------- fp16 tensor-core GEMM ----------------
// C = A[M,K] * W[N,K]^T + bias ; A,W half.
// layout 1: row-major fp32 into Cf. layout 0: half scatter to (b,h,s,d) into Ch,
// rope!=0 fuses reference-quirk RoPE (angle depends on batch index).
#define BM 256
#define BN 128
#define BK 64
#define SKH 72                         // halves per smem row (144B, conflict-free ldmatrix)
#define STG_A (BM * SKH)
#define STG_B (BN * SKH)
#define STG_H (STG_A + STG_B)
#define NSTAGE 4
#define GEMM_SMEM (NSTAGE * STG_H * 2)   // 221184 B

__global__ __launch_bounds__(512, 1) void gemm_fp16(
    const __half* __restrict__ A, const __half* __restrict__ W,
    const float* __restrict__ bias, float* __restrict__ Cf,
    __half* __restrict__ Ch, int layout, int rope)
{
    extern __shared__ __half sm[];

    const int tid  = threadIdx.x;
    const int lane = tid & 31, warp = tid >> 5;
    const int wm = warp >> 2, wn = warp & 3;       // 4x4 warps, warp tile 64x32
    const int g  = lane >> 2, tg = lane & 3;
    const int seg = lane >> 3, r8 = lane & 7;
    const int m0 = blockIdx.y * BM, n0 = blockIdx.x * BN;
    const int lc = tid & 7, lr = tid >> 3;         // 8 chunks x 64 rows per pass

    float acc[4][4][4];
    #pragma unroll
    for (int i = 0; i < 4; i++)
        #pragma unroll
        for (int j = 0; j < 4; j++)
            #pragma unroll
            for (int l = 0; l < 4; l++) acc[i][j][l] = 0.f;

    auto load_stage = [&](int kt) {
        const int st = kt & (NSTAGE - 1);
        const int k0 = kt * BK;
        __half* as = sm + st * STG_H;
        __half* bs = as + STG_A;
        #pragma unroll
        for (int i = 0; i < 4; i++) {              // A: 256 rows
            int r = lr + i * 64;
            cp16(&as[r * SKH + lc * 8], A + (size_t)(m0 + r) * DM + k0 + lc * 8);
        }
        #pragma unroll
        for (int i = 0; i < 2; i++) {              // B: 128 rows
            int r = lr + i * 64;
            cp16(&bs[r * SKH + lc * 8], W + (size_t)(n0 + r) * DM + k0 + lc * 8);
        }
        asm volatile("cp.async.commit_group;\n");
    };

    const int KT = DM / BK;    // 64
    load_stage(0);
    load_stage(1);
    load_stage(2);

    for (int kt = 0; kt < KT; kt++) {
        const int st = kt & (NSTAGE - 1);
        asm volatile("cp.async.wait_group 2;\n");
        __syncthreads();                            // stage st ready; stage st^3 free
        if (kt + 3 < KT) load_stage(kt + 3);        // overlaps with compute below

        const __half* as = sm + st * STG_H;
        const __half* bs = as + STG_A;
        #pragma unroll
        for (int ks = 0; ks < BK / 16; ks++) {      // 4 k16 steps
            unsigned a[4][4], b[2][4];
            #pragma unroll
            for (int mi = 0; mi < 4; mi++) {
                int row = wm * 64 + mi * 16 + (seg & 1) * 8 + r8;
                int col = ks * 16 + (seg >> 1) * 8;
                ldsm4(a[mi][0], a[mi][1], a[mi][2], a[mi][3], &as[row * SKH + col]);
            }
            #pragma unroll
            for (int nj = 0; nj < 2; nj++) {        // each x4: two n8 tiles of k16
                int row = wn * 32 + nj * 16 + (seg >> 1) * 8 + r8;
                int col = ks * 16 + (seg & 1) * 8;
                ldsm4(b[nj][0], b[nj][1], b[nj][2], b[nj][3], &bs[row * SKH + col]);
            }
            #pragma unroll
            for (int mi = 0; mi < 4; mi++)
                #pragma unroll
                for (int ni = 0; ni < 4; ni++)
                    mma16(acc[mi][ni], a[mi],
                          b[ni >> 1][(ni & 1) * 2], b[ni >> 1][(ni & 1) * 2 + 1]);
        }
    }

    // Epilogue: bias (+ optional fused RoPE) + layout
    #pragma unroll
    for (int mi = 0; mi < 4; mi++)
        #pragma unroll
        for (int ni = 0; ni < 4; ni++)
            #pragma unroll
            for (int hh = 0; hh < 2; hh++) {
                int row = m0 + wm * 64 + mi * 16 + hh * 8 + g;
                int col = n0 + wn * 32 + ni * 8 + tg * 2;
                float vx = acc[mi][ni][hh * 2 + 0] + bias[col];
                float vy = acc[mi][ni][hh * 2 + 1] + bias[col + 1];
                if (layout) {
                    *(float2*)(Cf + (size_t)row * DM + col) = make_float2(vx, vy);
                } else {
                    if (rope) {
                        // reference quirk: angle depends on BATCH index; m = s*32 + (d%64)/2
                        int bb = row >> 6, ss = row & 63;
                        int m = ss * 32 + ((col & 63) >> 1);
                        float ang = (float)bb * exp2f((float)m * (-13.287712379549449f / 2048.0f));
                        float sn, cs;
                        sincosf(ang, &sn, &cs);
                        float rx = vx * cs - vy * sn, ry = vx * sn + vy * cs;
                        vx = rx; vy = ry;
                    }
                    size_t idx = ((size_t)(row >> 6) * 64 + (col >> 6)) * 4096 +
                                 (size_t)(row & 63) * 64 + (col & 63);
                    __half2 hv = __floats2half2_rn(vx, vy);
                    *(__half2*)(Ch + idx) = hv;
                }
            }
}

// ---------------- fp32 -> fp16 conversion (2 float4 / thread) ----------------
__global__ void cvt_h(const float4* __restrict__ in, uint2* __restrict__ out)
{
    size_t i = ((size_t)blockIdx.x * blockDim.x + threadIdx.x) * 2;
    #pragma unroll
    for (int j = 0; j < 2; j++) {
        float4 v = in[i + j];
        __half2 lo = __floats2half2_rn(v.x, v.y);
        __half2 hi = __floats2half2_rn(v.z, v.w);
        out[i + j] = make_uint2(*(unsigned*)&lo, *(unsigned*)&hi);
    }
}

// ---------------- attention: one block per (b,h), fp32 math, half in/out ----------------
__global__ __launch_bounds__(256) void attn_kernel(
    const __half* __restrict__ q, const __half* __restrict__ k,
    const __half* __restrict__ v, __half* __restrict__ o)
{
    __shared__ float ps[64][65];   // Q, then P
    __shared__ float ks[64][65];   // K, then V
    const int tid = threadIdx.x;
    const size_t base = (size_t)blockIdx.x * 4096;

    for (int i = tid; i < 4096; i += 256) {
        ps[i >> 6][i & 63] = __half2float(q[base + i]);
        ks[i >> 6][i & 63] = __half2float(k[base + i]);
    }
    __syncthreads();

    const int r = tid >> 2, quad = tid & 3, c0 = quad * 16;
    float s[16];
    #pragma unroll
    for (int j = 0; j < 16; j++) s[j] = 0.f;
    for (int d = 0; d < 64; d++) {
        float qv = ps[r][d];
        #pragma unroll
        for (int j = 0; j < 16; j++) s[j] += qv * ks[c0 + j][d];
    }
    float mx = -1e30f;
    #pragma unroll
    for (int j = 0; j < 16; j++) { s[j] *= 0.125f; mx = fmaxf(mx, s[j]); }
    mx = fmaxf(mx, __shfl_xor_sync(0xffffffffu, mx, 1));
    mx = fmaxf(mx, __shfl_xor_sync(0xffffffffu, mx, 2));
    float sum = 0.f;
    #pragma unroll
    for (int j = 0; j < 16; j++) { s[j] = __expf(s[j] - mx); sum += s[j]; }
    sum += __shfl_xor_sync(0xffffffffu, sum, 1);
    sum += __shfl_xor_sync(0xffffffffu, sum, 2);
    float inv = 1.0f / sum;

    __syncthreads();
    #pragma unroll
    for (int j = 0; j < 16; j++) ps[r][c0 + j] = s[j] * inv;
    for (int i = tid; i < 4096; i += 256) ks[i >> 6][i & 63] = __half2float(v[base + i]);
    __syncthreads();

    float oacc[16];
    #pragma unroll
    for (int j = 0; j < 16; j++) oacc[j] = 0.f;
    for (int kk = 0; kk < 64; kk++) {
        float p = ps[r][kk];
        #pragma unroll
        for (int j = 0; j < 16; j++) oacc[j] += p * ks[kk][c0 + j];
    }

    const int bh = blockIdx.x, bb = bh >> 6, h = bh & 63;
    size_t ob = ((size_t)(bb * 64 + r)) * 4096 + h * 64 + c0;  // (b,s,h,d) token-major
    #pragma unroll
    for (int j = 0; j < 16; j++) o[ob + j] = __float2half_rn(oacc[j]);
}

extern "C" void kernel_launch(void* const* d_in, const int* in_sizes, int n_in,
                              void* d_out, int out_size)
{
    const float* x  = (const float*)d_in[0];
    const float* wq = (const float*)d_in[1];
    const float* bq = (const float*)d_in[2];
    const float* wk = (const float*)d_in[3];
    const float* bk = (const float*)d_in[4];
    const float* wv = (const float*)d_in[5];
    const float* bv = (const float*)d_in[6];
    const float* wo = (const float*)d_in[7];
    const float* bo = (const float*)d_in[8];
    float* out = (float*)d_out;

    __half *q, *k, *v, *ah, *xh, *wqh, *wkh, *wvh, *woh;
    cudaGetSymbolAddress((void**)&q,   g_q);
    cudaGetSymbolAddress((void**)&k,   g_k);
    cudaGetSymbolAddress((void**)&v,   g_v);
    cudaGetSymbolAddress((void**)&ah,  g_ah);
    cudaGetSymbolAddress((void**)&xh,  g_xh);
    cudaGetSymbolAddress((void**)&wqh, g_wqh);
    cudaGetSymbolAddress((void**)&wkh, g_wkh);
    cudaGetSymbolAddress((void**)&wvh, g_wvh);
    cudaGetSymbolAddress((void**)&woh, g_woh);

    cudaFuncSetAttribute(gemm_fp16, cudaFuncAttributeMaxDynamicSharedMemorySize, GEMM_SMEM);

    const int CVG = NELEM / 8 / 256;   // 8192
    dim3 gg(DM / BN, TOKS / BM);       // (32, 16)

    // All conversions first (so ncu -s 5 profiles the first GEMM)
    cvt_h<<<CVG, 256>>>((const float4*)x,  (uint2*)xh);
    cvt_h<<<CVG, 256>>>((const float4*)wq, (uint2*)wqh);
    cvt_h<<<CVG, 256>>>((const float4*)wk, (uint2*)wkh);
    cvt_h<<<CVG, 256>>>((const float4*)wv, (uint2*)wvh);
    cvt_h<<<CVG, 256>>>((const float4*)wo, (uint2*)woh);

    gemm_fp16<<<gg, 512, GEMM_SMEM>>>(xh, wqh, bq, nullptr, q, 0, 1);
    gemm_fp16<<<gg, 512, GEMM_SMEM>>>(xh, wkh, bk, nullptr, k, 0, 1);
    gemm_fp16<<<gg, 512, GEMM_SMEM>>>(xh, wvh, bv, nullptr, v, 0, 0);
    attn_kernel<<<4096, 256>>>(q, k, v, ah);
    gemm_fp16<<<gg, 512, GEMM_SMEM>>>(ah, woh, bo, out, nullptr, 1, 0);
}

// round 12
// speedup vs baseline: 1.1405x; 1.1405x over previous
#include <cuda_runtime.h>
#include <cuda_fp16.h>
#include <cstdint>

#define DM 4096
#define TOKS 4096
#define NELEM (TOKS * DM)

// Scratch (allocation-free rule: __device__ globals)
__device__ __half g_q[NELEM];    // Q (b,h,s,d) half
__device__ __half g_k[NELEM];    // K (b,h,s,d) half
__device__ __half g_v[NELEM];    // V (b,h,s,d) half
__device__ __half g_ah[NELEM];   // attention output (b,s,h,d) half
__device__ __half g_xh[NELEM];   // half activations
__device__ __half g_wqh[NELEM];
__device__ __half g_wkh[NELEM];
__device__ __half g_wvh[NELEM];
__device__ __half g_woh[NELEM];

__device__ __forceinline__ void ldsm4(unsigned &d0, unsigned &d1, unsigned &d2, unsigned &d3,
                                      const void *p) {
    uint32_t addr = (uint32_t)__cvta_generic_to_shared(p);
    asm volatile("ldmatrix.sync.aligned.m8n8.x4.shared.b16 {%0,%1,%2,%3}, [%4];"
                 : "=r"(d0), "=r"(d1), "=r"(d2), "=r"(d3)
                 : "r"(addr));
}

__device__ __forceinline__ void mma16(float c[4], const unsigned a[4], unsigned b0, unsigned b1) {
    asm volatile("mma.sync.aligned.m16n8k16.row.col.f32.f16.f16.f32 "
                 "{%0,%1,%2,%3}, {%4,%5,%6,%7}, {%8,%9}, {%0,%1,%2,%3};"
                 : "+f"(c[0]), "+f"(c[1]), "+f"(c[2]), "+f"(c[3])
                 : "r"(a[0]), "r"(a[1]), "r"(a[2]), "r"(a[3]), "r"(b0), "r"(b1));
}

__device__ __forceinline__ void cp16(void *smem_dst, const void *gsrc) {
    uint32_t d = (uint32_t)__cvta_generic_to_shared(smem_dst);
    asm volatile("cp.async.cg.shared.global [%0], [%1], 16;\n" :: "r"(d), "l"(gsrc));
}

// ---------------- fp16 tensor-core GEMM (R7 shape: 128x128, 3 stages, occ 2) ----------------
#define BM 128
#define BN 128
#define BK 64
#define SKH 72                        // halves per smem row (144B stride, conflict-free)
#define STG_H (BM * SKH)
#define NSTAGE 3
#define GEMM_SMEM (NSTAGE * 2 * STG_H * 2)   // 110592 B

// ---- mainloop shared by both GEMM kernels (acc[2][8][4], 4x2 warps) ----
#define GEMM_MAINLOOP(Aptr, Wptr)                                                        \
    extern __shared__ __half sm[];                                                       \
    __half* As = sm;                                                                     \
    __half* Bs = sm + NSTAGE * STG_H;                                                    \
    const int tid  = threadIdx.x;                                                        \
    const int lane = tid & 31, warp = tid >> 5;                                          \
    const int wm = warp >> 1, wn = warp & 1;                                             \
    const int g  = lane >> 2, tg = lane & 3;                                             \
    const int seg = lane >> 3, r8 = lane & 7;                                            \
    const int m0 = blockIdx.y * BM, n0 = blockIdx.x * BN;                                \
    const int lc = tid & 7, lr = tid >> 3;                                               \
    float acc[2][8][4];                                                                  \
    _Pragma("unroll")                                                                    \
    for (int i = 0; i < 2; i++)                                                          \
        _Pragma("unroll")                                                                \
        for (int j = 0; j < 8; j++)                                                      \
            _Pragma("unroll")                                                            \
            for (int l = 0; l < 4; l++) acc[i][j][l] = 0.f;                              \
    auto load_stage = [&](int kt) {                                                      \
        const int st = kt % NSTAGE;                                                      \
        const int k0 = kt * BK;                                                          \
        __half* as = As + st * STG_H;                                                    \
        __half* bs = Bs + st * STG_H;                                                    \
        _Pragma("unroll")                                                                \
        for (int i = 0; i < 4; i++) {                                                    \
            int r = lr + i * 32;                                                         \
            cp16(&as[r * SKH + lc * 8], (Aptr) + (size_t)(m0 + r) * DM + k0 + lc * 8);   \
            cp16(&bs[r * SKH + lc * 8], (Wptr) + (size_t)(n0 + r) * DM + k0 + lc * 8);   \
        }                                                                                \
        asm volatile("cp.async.commit_group;\n");                                        \
    };                                                                                   \
    const int KT = DM / BK;                                                              \
    load_stage(0);                                                                       \
    load_stage(1);                                                                       \
    for (int kt = 0; kt < KT; kt++) {                                                    \
        const int st = kt % NSTAGE;                                                      \
        asm volatile("cp.async.wait_group 1;\n");                                        \
        __syncthreads();                                                                 \
        if (kt + 2 < KT) load_stage(kt + 2);                                             \
        const __half* as = As + st * STG_H;                                              \
        const __half* bs = Bs + st * STG_H;                                              \
        _Pragma("unroll")                                                                \
        for (int ks = 0; ks < BK / 16; ks++) {                                           \
            unsigned a[2][4], b[4][4];                                                   \
            _Pragma("unroll")                                                            \
            for (int mi = 0; mi < 2; mi++) {                                             \
                int row = wm * 32 + mi * 16 + (seg & 1) * 8 + r8;                        \
                int col = ks * 16 + (seg >> 1) * 8;                                      \
                ldsm4(a[mi][0], a[mi][1], a[mi][2], a[mi][3], &as[row * SKH + col]);     \
            }                                                                            \
            _Pragma("unroll")                                                            \
            for (int nj = 0; nj < 4; nj++) {                                             \
                int row = wn * 64 + nj * 16 + (seg >> 1) * 8 + r8;                       \
                int col = ks * 16 + (seg & 1) * 8;                                       \
                ldsm4(b[nj][0], b[nj][1], b[nj][2], b[nj][3], &bs[row * SKH + col]);     \
            }                                                                            \
            _Pragma("unroll")                                                            \
            for (int mi = 0; mi < 2; mi++)                                               \
                _Pragma("unroll")                                                        \
                for (int ni = 0; ni < 8; ni++)                                           \
                    mma16(acc[mi][ni], a[mi],                                            \
                          b[ni >> 1][(ni & 1) * 2], b[ni >> 1][(ni & 1) * 2 + 1]);       \
        }                                                                                \
    }

// QKV batched GEMM: blockIdx.z selects {W, bias, out, rope}; out half, (b,h,s,d) scatter
__global__ __launch_bounds__(256, 2) void gemm_qkv(
    const __half* __restrict__ A,
    const __half* __restrict__ W0, const __half* __restrict__ W1, const __half* __restrict__ W2,
    const float* __restrict__ b0, const float* __restrict__ b1, const float* __restrict__ b2,
    __half* __restrict__ C0, __half* __restrict__ C1, __half* __restrict__ C2)
{
    const int z = blockIdx.z;
    const __half* Wz = (z == 0) ? W0 : (z == 1) ? W1 : W2;
    const float*  bz = (z == 0) ? b0 : (z == 1) ? b1 : b2;
    __half*       Cz = (z == 0) ? C0 : (z == 1) ? C1 : C2;
    const bool rope = (z < 2);

    GEMM_MAINLOOP(A, Wz)

    #pragma unroll
    for (int mi = 0; mi < 2; mi++)
        #pragma unroll
        for (int ni = 0; ni < 8; ni++)
            #pragma unroll
            for (int hh = 0; hh < 2; hh++) {
                int row = m0 + wm * 32 + mi * 16 + hh * 8 + g;
                int col = n0 + wn * 64 + ni * 8 + tg * 2;
                float vx = acc[mi][ni][hh * 2 + 0] + bz[col];
                float vy = acc[mi][ni][hh * 2 + 1] + bz[col + 1];
                if (rope) {
                    // reference quirk: angle depends on BATCH index; m = s*32 + (d%64)/2
                    int bb = row >> 6, ss = row & 63;
                    int m = ss * 32 + ((col & 63) >> 1);
                    float ang = (float)bb * exp2f((float)m * (-13.287712379549449f / 2048.0f));
                    float sn, cs;
                    sincosf(ang, &sn, &cs);
                    float rx = vx * cs - vy * sn, ry = vx * sn + vy * cs;
                    vx = rx; vy = ry;
                }
                size_t idx = ((size_t)(row >> 6) * 64 + (col >> 6)) * 4096 +
                             (size_t)(row & 63) * 64 + (col & 63);
                *(__half2*)(Cz + idx) = __floats2half2_rn(vx, vy);
            }
}

// O GEMM: fp32 row-major output (final result)
__global__ __launch_bounds__(256, 2) void gemm_o(
    const __half* __restrict__ A, const __half* __restrict__ W,
    const float* __restrict__ bias, float* __restrict__ C)
{
    GEMM_MAINLOOP(A, W)

    #pragma unroll
    for (int mi = 0; mi < 2; mi++)
        #pragma unroll
        for (int ni = 0; ni < 8; ni++)
            #pragma unroll
            for (int hh = 0; hh < 2; hh++) {
                int row = m0 + wm * 32 + mi * 16 + hh * 8 + g;
                int col = n0 + wn * 64 + ni * 8 + tg * 2;
                float2 v;
                v.x = acc[mi][ni][hh * 2 + 0] + bias[col];
                v.y = acc[mi][ni][hh * 2 + 1] + bias[col + 1];
                *(float2*)(C + (size_t)row * DM + col) = v;
            }
}

// ---------------- fp32 -> fp16 conversion ----------------
__global__ void cvt_h(const float4* __restrict__ in, uint2* __restrict__ out)
{
    size_t i = ((size_t)blockIdx.x * blockDim.x + threadIdx.x) * 2;
    #pragma unroll
    for (int j = 0; j < 2; j++) {
        float4 v = in[i + j];
        __half2 lo = __floats2half2_rn(v.x, v.y);
        __half2 hi = __floats2half2_rn(v.z, v.w);
        out[i + j] = make_uint2(*(unsigned*)&lo, *(unsigned*)&hi);
    }
}

// batched weight conversion: blockIdx.y selects which weight matrix
__global__ void cvt_w4(const float4* __restrict__ w0, const float4* __restrict__ w1,
                       const float4* __restrict__ w2, const float4* __restrict__ w3,
                       uint2* __restrict__ o0, uint2* __restrict__ o1,
                       uint2* __restrict__ o2, uint2* __restrict__ o3)
{
    const int z = blockIdx.y;
    const float4* in = (z == 0) ? w0 : (z == 1) ? w1 : (z == 2) ? w2 : w3;
    uint2* out = (z == 0) ? o0 : (z == 1) ? o1 : (z == 2) ? o2 : o3;
    size_t i = ((size_t)blockIdx.x * blockDim.x + threadIdx.x) * 2;
    #pragma unroll
    for (int j = 0; j < 2; j++) {
        float4 v = in[i + j];
        __half2 lo = __floats2half2_rn(v.x, v.y);
        __half2 hi = __floats2half2_rn(v.z, v.w);
        out[i + j] = make_uint2(*(unsigned*)&lo, *(unsigned*)&hi);
    }
}

// ---------------- attention: one block per (b,h), fp32 math, half in/out ----------------
__global__ __launch_bounds__(256) void attn_kernel(
    const __half* __restrict__ q, const __half* __restrict__ k,
    const __half* __restrict__ v, __half* __restrict__ o)
{
    __shared__ float ps[64][65];   // Q, then P
    __shared__ float ks[64][65];   // K, then V
    const int tid = threadIdx.x;
    const size_t base = (size_t)blockIdx.x * 4096;

    for (int i = tid; i < 4096; i += 256) {
        ps[i >> 6][i & 63] = __half2float(q[base + i]);
        ks[i >> 6][i & 63] = __half2float(k[base + i]);
    }
    __syncthreads();

    const int r = tid >> 2, quad = tid & 3, c0 = quad * 16;
    float s[16];
    #pragma unroll
    for (int j = 0; j < 16; j++) s[j] = 0.f;
    for (int d = 0; d < 64; d++) {
        float qv = ps[r][d];
        #pragma unroll
        for (int j = 0; j < 16; j++) s[j] += qv * ks[c0 + j][d];
    }
    float mx = -1e30f;
    #pragma unroll
    for (int j = 0; j < 16; j++) { s[j] *= 0.125f; mx = fmaxf(mx, s[j]); }
    mx = fmaxf(mx, __shfl_xor_sync(0xffffffffu, mx, 1));
    mx = fmaxf(mx, __shfl_xor_sync(0xffffffffu, mx, 2));
    float sum = 0.f;
    #pragma unroll
    for (int j = 0; j < 16; j++) { s[j] = __expf(s[j] - mx); sum += s[j]; }
    sum += __shfl_xor_sync(0xffffffffu, sum, 1);
    sum += __shfl_xor_sync(0xffffffffu, sum, 2);
    float inv = 1.0f / sum;

    __syncthreads();
    #pragma unroll
    for (int j = 0; j < 16; j++) ps[r][c0 + j] = s[j] * inv;
    for (int i = tid; i < 4096; i += 256) ks[i >> 6][i & 63] = __half2float(v[base + i]);
    __syncthreads();

    float oacc[16];
    #pragma unroll
    for (int j = 0; j < 16; j++) oacc[j] = 0.f;
    for (int kk = 0; kk < 64; kk++) {
        float p = ps[r][kk];
        #pragma unroll
        for (int j = 0; j < 16; j++) oacc[j] += p * ks[kk][c0 + j];
    }

    const int bh = blockIdx.x, bb = bh >> 6, h = bh & 63;
    size_t ob = ((size_t)(bb * 64 + r)) * 4096 + h * 64 + c0;  // (b,s,h,d) token-major
    #pragma unroll
    for (int j = 0; j < 16; j++) o[ob + j] = __float2half_rn(oacc[j]);
}

extern "C" void kernel_launch(void* const* d_in, const int* in_sizes, int n_in,
                              void* d_out, int out_size)
{
    const float* x  = (const float*)d_in[0];
    const float* wq = (const float*)d_in[1];
    const float* bq = (const float*)d_in[2];
    const float* wk = (const float*)d_in[3];
    const float* bk = (const float*)d_in[4];
    const float* wv = (const float*)d_in[5];
    const float* bv = (const float*)d_in[6];
    const float* wo = (const float*)d_in[7];
    const float* bo = (const float*)d_in[8];
    float* out = (float*)d_out;

    __half *q, *k, *v, *ah, *xh, *wqh, *wkh, *wvh, *woh;
    cudaGetSymbolAddress((void**)&q,   g_q);
    cudaGetSymbolAddress((void**)&k,   g_k);
    cudaGetSymbolAddress((void**)&v,   g_v);
    cudaGetSymbolAddress((void**)&ah,  g_ah);
    cudaGetSymbolAddress((void**)&xh,  g_xh);
    cudaGetSymbolAddress((void**)&wqh, g_wqh);
    cudaGetSymbolAddress((void**)&wkh, g_wkh);
    cudaGetSymbolAddress((void**)&wvh, g_wvh);
    cudaGetSymbolAddress((void**)&woh, g_woh);

    cudaFuncSetAttribute(gemm_qkv, cudaFuncAttributeMaxDynamicSharedMemorySize, GEMM_SMEM);
    cudaFuncSetAttribute(gemm_o,   cudaFuncAttributeMaxDynamicSharedMemorySize, GEMM_SMEM);

    const int CVG = NELEM / 8 / 256;       // 8192
    dim3 gqkv(DM / BN, TOKS / BM, 3);      // (32, 32, 3)
    dim3 go(DM / BN, TOKS / BM);           // (32, 32)

    cvt_h<<<CVG, 256>>>((const float4*)x, (uint2*)xh);
    cvt_w4<<<dim3(CVG, 4), 256>>>((const float4*)wq, (const float4*)wk,
                                  (const float4*)wv, (const float4*)wo,
                                  (uint2*)wqh, (uint2*)wkh, (uint2*)wvh, (uint2*)woh);
    gemm_qkv<<<gqkv, 256, GEMM_SMEM>>>(xh, wqh, wkh, wvh, bq, bk, bv, q, k, v);
    attn_kernel<<<4096, 256>>>(q, k, v, ah);
    gemm_o<<<go, 256, GEMM_SMEM>>>(ah, woh, bo, out);
}

// round 15
// speedup vs baseline: 1.5116x; 1.3253x over previous
#include <cuda_runtime.h>
#include <cuda_fp16.h>
#include <cstdint>

#define DM 4096
#define TOKS 4096
#define NELEM (TOKS * DM)

// Scratch (allocation-free rule: __device__ globals)
__device__ __half g_q[NELEM];    // Q (b,h,s,d) half
__device__ __half g_k[NELEM];    // K (b,h,s,d) half
__device__ __half g_v[NELEM];    // V (b,h,s,d) half
__device__ __half g_ah[NELEM];   // attention output (b,s,h,d) half
__device__ __half g_xh[NELEM];   // half activations
__device__ __half g_wqh[NELEM];
__device__ __half g_wkh[NELEM];
__device__ __half g_wvh[NELEM];
__device__ __half g_woh[NELEM];

__device__ __forceinline__ void ldsm4(unsigned &d0, unsigned &d1, unsigned &d2, unsigned &d3,
                                      const void *p) {
    uint32_t addr = (uint32_t)__cvta_generic_to_shared(p);
    asm volatile("ldmatrix.sync.aligned.m8n8.x4.shared.b16 {%0,%1,%2,%3}, [%4];"
                 : "=r"(d0), "=r"(d1), "=r"(d2), "=r"(d3)
                 : "r"(addr));
}

__device__ __forceinline__ void ldsm4t(unsigned &d0, unsigned &d1, unsigned &d2, unsigned &d3,
                                       const void *p) {
    uint32_t addr = (uint32_t)__cvta_generic_to_shared(p);
    asm volatile("ldmatrix.sync.aligned.m8n8.x4.trans.shared.b16 {%0,%1,%2,%3}, [%4];"
                 : "=r"(d0), "=r"(d1), "=r"(d2), "=r"(d3)
                 : "r"(addr));
}

__device__ __forceinline__ void mma16(float c[4], const unsigned a[4], unsigned b0, unsigned b1) {
    asm volatile("mma.sync.aligned.m16n8k16.row.col.f32.f16.f16.f32 "
                 "{%0,%1,%2,%3}, {%4,%5,%6,%7}, {%8,%9}, {%0,%1,%2,%3};"
                 : "+f"(c[0]), "+f"(c[1]), "+f"(c[2]), "+f"(c[3])
                 : "r"(a[0]), "r"(a[1]), "r"(a[2]), "r"(a[3]), "r"(b0), "r"(b1));
}

__device__ __forceinline__ void cp16(void *smem_dst, const void *gsrc) {
    uint32_t d = (uint32_t)__cvta_generic_to_shared(smem_dst);
    asm volatile("cp.async.cg.shared.global [%0], [%1], 16;\n" :: "r"(d), "l"(gsrc));
}

__device__ __forceinline__ unsigned h2pack(float x, float y) {
    __half2 h = __floats2half2_rn(x, y);
    return *(unsigned*)&h;
}

// ---------------- fp16 tensor-core GEMM (128x128, 3 stages, occ 2) ----------------
#define BM 128
#define BN 128
#define BK 64
#define SKH 72                        // halves per smem row (144B stride, conflict-free)
#define STG_H (BM * SKH)
#define NSTAGE 3
#define GEMM_SMEM (NSTAGE * 2 * STG_H * 2)   // 110592 B

#define GEMM_MAINLOOP(Aptr, Wptr)                                                        \
    extern __shared__ __half sm[];                                                       \
    __half* As = sm;                                                                     \
    __half* Bs = sm + NSTAGE * STG_H;                                                    \
    const int tid  = threadIdx.x;                                                        \
    const int lane = tid & 31, warp = tid >> 5;                                          \
    const int wm = warp >> 1, wn = warp & 1;                                             \
    const int g  = lane >> 2, tg = lane & 3;                                             \
    const int seg = lane >> 3, r8 = lane & 7;                                            \
    const int m0 = blockIdx.y * BM, n0 = blockIdx.x * BN;                                \
    const int lc = tid & 7, lr = tid >> 3;                                               \
    float acc[2][8][4];                                                                  \
    _Pragma("unroll")                                                                    \
    for (int i = 0; i < 2; i++)                                                          \
        _Pragma("unroll")                                                                \
        for (int j = 0; j < 8; j++)                                                      \
            _Pragma("unroll")                                                            \
            for (int l = 0; l < 4; l++) acc[i][j][l] = 0.f;                              \
    auto load_stage = [&](int kt) {                                                      \
        const int st = kt % NSTAGE;                                                      \
        const int k0 = kt * BK;                                                          \
        __half* as = As + st * STG_H;                                                    \
        __half* bs = Bs + st * STG_H;                                                    \
        _Pragma("unroll")                                                                \
        for (int i = 0; i < 4; i++) {                                                    \
            int r = lr + i * 32;                                                         \
            cp16(&as[r * SKH + lc * 8], (Aptr) + (size_t)(m0 + r) * DM + k0 + lc * 8);   \
            cp16(&bs[r * SKH + lc * 8], (Wptr) + (size_t)(n0 + r) * DM + k0 + lc * 8);   \
        }                                                                                \
        asm volatile("cp.async.commit_group;\n");                                        \
    };                                                                                   \
    const int KT = DM / BK;                                                              \
    load_stage(0);                                                                       \
    load_stage(1);                                                                       \
    for (int kt = 0; kt < KT; kt++) {                                                    \
        const int st = kt % NSTAGE;                                                      \
        asm volatile("cp.async.wait_group 1;\n");                                        \
        __syncthreads();                                                                 \
        if (kt + 2 < KT) load_stage(kt + 2);                                             \
        const __half* as = As + st * STG_H;                                              \
        const __half* bs = Bs + st * STG_H;                                              \
        _Pragma("unroll")                                                                \
        for (int ks = 0; ks < BK / 16; ks++) {                                           \
            unsigned a[2][4], b[4][4];                                                   \
            _Pragma("unroll")                                                            \
            for (int mi = 0; mi < 2; mi++) {                                             \
                int row = wm * 32 + mi * 16 + (seg & 1) * 8 + r8;                        \
                int col = ks * 16 + (seg >> 1) * 8;                                      \
                ldsm4(a[mi][0], a[mi][1], a[mi][2], a[mi][3], &as[row * SKH + col]);     \
            }                                                                            \
            _Pragma("unroll")                                                            \
            for (int nj = 0; nj < 4; nj++) {                                             \
                int row = wn * 64 + nj * 16 + (seg >> 1) * 8 + r8;                       \
                int col = ks * 16 + (seg & 1) * 8;                                       \
                ldsm4(b[nj][0], b[nj][1], b[nj][2], b[nj][3], &bs[row * SKH + col]);     \
            }                                                                            \
            _Pragma("unroll")                                                            \
            for (int mi = 0; mi < 2; mi++)                                               \
                _Pragma("unroll")                                                        \
                for (int ni = 0; ni < 8; ni++)                                           \
                    mma16(acc[mi][ni], a[mi],                                            \
                          b[ni >> 1][(ni & 1) * 2], b[ni >> 1][(ni & 1) * 2 + 1]);       \
        }                                                                                \
    }

// QKV batched GEMM: blockIdx.z selects {W, bias, out, rope}; out half, (b,h,s,d) scatter
__global__ __launch_bounds__(256, 2) void gemm_qkv(
    const __half* __restrict__ A,
    const __half* __restrict__ W0, const __half* __restrict__ W1, const __half* __restrict__ W2,
    const float* __restrict__ b0, const float* __restrict__ b1, const float* __restrict__ b2,
    __half* __restrict__ C0, __half* __restrict__ C1, __half* __restrict__ C2)
{
    const int z = blockIdx.z;
    const __half* Wz = (z == 0) ? W0 : (z == 1) ? W1 : W2;
    const float*  bz = (z == 0) ? b0 : (z == 1) ? b1 : b2;
    __half*       Cz = (z == 0) ? C0 : (z == 1) ? C1 : C2;
    const bool rope = (z < 2);

    GEMM_MAINLOOP(A, Wz)

    #pragma unroll
    for (int mi = 0; mi < 2; mi++)
        #pragma unroll
        for (int ni = 0; ni < 8; ni++)
            #pragma unroll
            for (int hh = 0; hh < 2; hh++) {
                int row = m0 + wm * 32 + mi * 16 + hh * 8 + g;
                int col = n0 + wn * 64 + ni * 8 + tg * 2;
                float vx = acc[mi][ni][hh * 2 + 0] + bz[col];
                float vy = acc[mi][ni][hh * 2 + 1] + bz[col + 1];
                if (rope) {
                    // reference quirk: angle depends on BATCH index; m = s*32 + (d%64)/2
                    int bb = row >> 6, ss = row & 63;
                    int m = ss * 32 + ((col & 63) >> 1);
                    float ang = (float)bb * exp2f((float)m * (-13.287712379549449f / 2048.0f));
                    float sn, cs;
                    sincosf(ang, &sn, &cs);
                    float rx = vx * cs - vy * sn, ry = vx * sn + vy * cs;
                    vx = rx; vy = ry;
                }
                size_t idx = ((size_t)(row >> 6) * 64 + (col >> 6)) * 4096 +
                             (size_t)(row & 63) * 64 + (col & 63);
                *(__half2*)(Cz + idx) = __floats2half2_rn(vx, vy);
            }
}

// O GEMM: fp32 row-major output (final result)
__global__ __launch_bounds__(256, 2) void gemm_o(
    const __half* __restrict__ A, const __half* __restrict__ W,
    const float* __restrict__ bias, float* __restrict__ C)
{
    GEMM_MAINLOOP(A, W)

    #pragma unroll
    for (int mi = 0; mi < 2; mi++)
        #pragma unroll
        for (int ni = 0; ni < 8; ni++)
            #pragma unroll
            for (int hh = 0; hh < 2; hh++) {
                int row = m0 + wm * 32 + mi * 16 + hh * 8 + g;
                int col = n0 + wn * 64 + ni * 8 + tg * 2;
                float2 v;
                v.x = acc[mi][ni][hh * 2 + 0] + bias[col];
                v.y = acc[mi][ni][hh * 2 + 1] + bias[col + 1];
                *(float2*)(C + (size_t)row * DM + col) = v;
            }
}

// ---------------- fp32 -> fp16 conversion ----------------
__global__ void cvt_h(const float4* __restrict__ in, uint2* __restrict__ out)
{
    size_t i = ((size_t)blockIdx.x * blockDim.x + threadIdx.x) * 2;
    #pragma unroll
    for (int j = 0; j < 2; j++) {
        float4 v = in[i + j];
        __half2 lo = __floats2half2_rn(v.x, v.y);
        __half2 hi = __floats2half2_rn(v.z, v.w);
        out[i + j] = make_uint2(*(unsigned*)&lo, *(unsigned*)&hi);
    }
}

__global__ void cvt_w4(const float4* __restrict__ w0, const float4* __restrict__ w1,
                       const float4* __restrict__ w2, const float4* __restrict__ w3,
                       uint2* __restrict__ o0, uint2* __restrict__ o1,
                       uint2* __restrict__ o2, uint2* __restrict__ o3)
{
    const int z = blockIdx.y;
    const float4* in = (z == 0) ? w0 : (z == 1) ? w1 : (z == 2) ? w2 : w3;
    uint2* out = (z == 0) ? o0 : (z == 1) ? o1 : (z == 2) ? o2 : o3;
    size_t i = ((size_t)blockIdx.x * blockDim.x + threadIdx.x) * 2;
    #pragma unroll
    for (int j = 0; j < 2; j++) {
        float4 v = in[i + j];
        __half2 lo = __floats2half2_rn(v.x, v.y);
        __half2 hi = __floats2half2_rn(v.z, v.w);
        out[i + j] = make_uint2(*(unsigned*)&lo, *(unsigned*)&hi);
    }
}

// ---------------- tensor-core attention: one block per (b,h) ----------------
// 4 warps; warp w owns rows w*16. S = Q@K^T (fp16 MMA, fp32 acc), softmax in
// registers, P stays in registers as A-fragments, O = P@V via ldmatrix.trans on V.
#define ASK 72   // padded smem stride (halves)

__global__ __launch_bounds__(128) void attn_tc(
    const __half* __restrict__ q, const __half* __restrict__ k,
    const __half* __restrict__ v, __half* __restrict__ o)
{
    __shared__ __half Qs[64 * ASK], Ks[64 * ASK], Vs[64 * ASK];
    const int tid = threadIdx.x, lane = tid & 31, warp = tid >> 5;
    const size_t base = (size_t)blockIdx.x * 4096;

    // Load Q,K,V tiles (64x64 half each) via cp.async
    #pragma unroll
    for (int c = 0; c < 4; c++) {
        int idx = tid + c * 128;              // 512 chunks of 8 halves per matrix
        int row = idx >> 3, col = (idx & 7) * 8;
        cp16(&Qs[row * ASK + col], q + base + row * 64 + col);
        cp16(&Ks[row * ASK + col], k + base + row * 64 + col);
        cp16(&Vs[row * ASK + col], v + base + row * 64 + col);
    }
    asm volatile("cp.async.commit_group;\ncp.async.wait_group 0;\n" ::: "memory");
    __syncthreads();

    const int seg = lane >> 3, r8 = lane & 7;
    const int g = lane >> 2, tg = lane & 3;

    // ---- S = Q @ K^T ----
    float accS[8][4];
    #pragma unroll
    for (int j = 0; j < 8; j++)
        #pragma unroll
        for (int l = 0; l < 4; l++) accS[j][l] = 0.f;

    #pragma unroll
    for (int ks = 0; ks < 4; ks++) {
        unsigned a[4], b[4][4];
        {
            int row = warp * 16 + (seg & 1) * 8 + r8;
            int col = ks * 16 + (seg >> 1) * 8;
            ldsm4(a[0], a[1], a[2], a[3], &Qs[row * ASK + col]);
        }
        #pragma unroll
        for (int nj = 0; nj < 4; nj++) {
            int row = nj * 16 + (seg >> 1) * 8 + r8;
            int col = ks * 16 + (seg & 1) * 8;
            ldsm4(b[nj][0], b[nj][1], b[nj][2], b[nj][3], &Ks[row * ASK + col]);
        }
        #pragma unroll
        for (int ni = 0; ni < 8; ni++)
            mma16(accS[ni], a, b[ni >> 1][(ni & 1) * 2], b[ni >> 1][(ni & 1) * 2 + 1]);
    }

    // ---- softmax in registers (rows g and g+8 of this warp's 16-row stripe) ----
    float mx0 = -1e30f, mx1 = -1e30f;
    #pragma unroll
    for (int nj = 0; nj < 8; nj++) {
        #pragma unroll
        for (int l = 0; l < 4; l++) accS[nj][l] *= 0.125f;
        mx0 = fmaxf(mx0, fmaxf(accS[nj][0], accS[nj][1]));
        mx1 = fmaxf(mx1, fmaxf(accS[nj][2], accS[nj][3]));
    }
    mx0 = fmaxf(mx0, __shfl_xor_sync(0xffffffffu, mx0, 1));
    mx0 = fmaxf(mx0, __shfl_xor_sync(0xffffffffu, mx0, 2));
    mx1 = fmaxf(mx1, __shfl_xor_sync(0xffffffffu, mx1, 1));
    mx1 = fmaxf(mx1, __shfl_xor_sync(0xffffffffu, mx1, 2));
    float s0 = 0.f, s1 = 0.f;
    #pragma unroll
    for (int nj = 0; nj < 8; nj++) {
        accS[nj][0] = __expf(accS[nj][0] - mx0); s0 += accS[nj][0];
        accS[nj][1] = __expf(accS[nj][1] - mx0); s0 += accS[nj][1];
        accS[nj][2] = __expf(accS[nj][2] - mx1); s1 += accS[nj][2];
        accS[nj][3] = __expf(accS[nj][3] - mx1); s1 += accS[nj][3];
    }
    s0 += __shfl_xor_sync(0xffffffffu, s0, 1);
    s0 += __shfl_xor_sync(0xffffffffu, s0, 2);
    s1 += __shfl_xor_sync(0xffffffffu, s1, 1);
    s1 += __shfl_xor_sync(0xffffffffu, s1, 2);
    float inv0 = 1.0f / s0, inv1 = 1.0f / s1;
    #pragma unroll
    for (int nj = 0; nj < 8; nj++) {
        accS[nj][0] *= inv0; accS[nj][1] *= inv0;
        accS[nj][2] *= inv1; accS[nj][3] *= inv1;
    }

    // ---- O = P @ V ; P converted from accumulators directly into A-fragments ----
    float accO[8][4];
    #pragma unroll
    for (int j = 0; j < 8; j++)
        #pragma unroll
        for (int l = 0; l < 4; l++) accO[j][l] = 0.f;

    #pragma unroll
    for (int ks = 0; ks < 4; ks++) {
        unsigned pa[4];
        pa[0] = h2pack(accS[2 * ks][0],     accS[2 * ks][1]);
        pa[1] = h2pack(accS[2 * ks][2],     accS[2 * ks][3]);
        pa[2] = h2pack(accS[2 * ks + 1][0], accS[2 * ks + 1][1]);
        pa[3] = h2pack(accS[2 * ks + 1][2], accS[2 * ks + 1][3]);
        unsigned b[4][4];
        #pragma unroll
        for (int nj = 0; nj < 4; nj++) {
            int row = ks * 16 + (seg & 1) * 8 + r8;     // k index into V rows
            int col = nj * 16 + (seg >> 1) * 8;         // d index
            ldsm4t(b[nj][0], b[nj][1], b[nj][2], b[nj][3], &Vs[row * ASK + col]);
        }
        #pragma unroll
        for (int ni = 0; ni < 8; ni++)
            mma16(accO[ni], pa, b[ni >> 1][(ni & 1) * 2], b[ni >> 1][(ni & 1) * 2 + 1]);
    }

    // ---- epilogue: write (b,s,h,d) token-major half ----
    const int bh = blockIdx.x, bb = bh >> 6, h = bh & 63;
    const int s_lo = warp * 16 + g;
    #pragma unroll
    for (int ni = 0; ni < 8; ni++) {
        int d = ni * 8 + tg * 2;
        size_t i0 = ((size_t)(bb * 64 + s_lo)) * 4096 + h * 64 + d;
        size_t i1 = ((size_t)(bb * 64 + s_lo + 8)) * 4096 + h * 64 + d;
        *(__half2*)(o + i0) = __floats2half2_rn(accO[ni][0], accO[ni][1]);
        *(__half2*)(o + i1) = __floats2half2_rn(accO[ni][2], accO[ni][3]);
    }
}

extern "C" void kernel_launch(void* const* d_in, const int* in_sizes, int n_in,
                              void* d_out, int out_size)
{
    const float* x  = (const float*)d_in[0];
    const float* wq = (const float*)d_in[1];
    const float* bq = (const float*)d_in[2];
    const float* wk = (const float*)d_in[3];
    const float* bk = (const float*)d_in[4];
    const float* wv = (const float*)d_in[5];
    const float* bv = (const float*)d_in[6];
    const float* wo = (const float*)d_in[7];
    const float* bo = (const float*)d_in[8];
    float* out = (float*)d_out;

    __half *q, *k, *v, *ah, *xh, *wqh, *wkh, *wvh, *woh;
    cudaGetSymbolAddress((void**)&q,   g_q);
    cudaGetSymbolAddress((void**)&k,   g_k);
    cudaGetSymbolAddress((void**)&v,   g_v);
    cudaGetSymbolAddress((void**)&ah,  g_ah);
    cudaGetSymbolAddress((void**)&xh,  g_xh);
    cudaGetSymbolAddress((void**)&wqh, g_wqh);
    cudaGetSymbolAddress((void**)&wkh, g_wkh);
    cudaGetSymbolAddress((void**)&wvh, g_wvh);
    cudaGetSymbolAddress((void**)&woh, g_woh);

    cudaFuncSetAttribute(gemm_qkv, cudaFuncAttributeMaxDynamicSharedMemorySize, GEMM_SMEM);
    cudaFuncSetAttribute(gemm_o,   cudaFuncAttributeMaxDynamicSharedMemorySize, GEMM_SMEM);

    const int CVG = NELEM / 8 / 256;       // 8192
    dim3 gqkv(DM / BN, TOKS / BM, 3);      // (32, 32, 3)
    dim3 go(DM / BN, TOKS / BM);           // (32, 32)

    cvt_h<<<CVG, 256>>>((const float4*)x, (uint2*)xh);
    cvt_w4<<<dim3(CVG, 4), 256>>>((const float4*)wq, (const float4*)wk,
                                  (const float4*)wv, (const float4*)wo,
                                  (uint2*)wqh, (uint2*)wkh, (uint2*)wvh, (uint2*)woh);
    gemm_qkv<<<gqkv, 256, GEMM_SMEM>>>(xh, wqh, wkh, wvh, bq, bk, bv, q, k, v);
    attn_tc<<<4096, 128>>>(q, k, v, ah);
    gemm_o<<<go, 256, GEMM_SMEM>>>(ah, woh, bo, out);
}